// round 10
// baseline (speedup 1.0000x reference)
#include <cuda_runtime.h>

typedef unsigned long long ull;

// 201 MB ping-pong scratch (allocation-free rule: __device__ global)
__device__ float g_buf[16u * 3u * 1024u * 1024u];
// pre-packed (w,w) f32x2 weights, layout [ci][kx][s=co*5+ky] padded to 16
__device__ ull   g_wpack[240];

__device__ __forceinline__ ull pack2(float lo, float hi) {
    ull r;
    asm("mov.b64 %0, {%1, %2};" : "=l"(r) : "f"(lo), "f"(hi));
    return r;
}
__device__ __forceinline__ float2 unpack2(ull v) {
    float2 r;
    asm("mov.b64 {%0, %1}, %2;" : "=f"(r.x), "=f"(r.y) : "l"(v));
    return r;
}
// packed fp32x2 FMA (FFMA2) -- only reachable via PTX fma.rn.f32x2
__device__ __forceinline__ void fma2(ull& d, ull a, ull b) {
    asm("fma.rn.f32x2 %0, %1, %2, %0;" : "+l"(d) : "l"(a), "l"(b));
}

// prep: broadcast-pack weights once; W is OIHW [co][ci][ky][kx] = [3][3][5][5]
__global__ void pack_w(const float* __restrict__ W) {
    int i = threadIdx.x;
    if (i >= 240) return;
    int ci = i / 80;
    int r  = i - ci * 80;
    int kx = r / 16;
    int s  = r - kx * 16;
    float w = 0.0f;
    if (s < 15) {
        int co = s / 5;
        int ky = s - co * 5;
        w = W[co * 75 + ci * 25 + ky * 5 + kx];
    }
    g_wpack[i] = pack2(w, w);
}

__device__ __forceinline__ void halo_load(const float* __restrict__ src,
                                          float2 (*smx)[12][132],
                                          int i, int xb, int rb, int img)
{
    // i in [0,144): 3ch x 12 pair-rows x 4 wrap columns
    int ch  = i / 48;
    int rem = i - ch * 48;
    int p   = rem >> 2;
    int j   = rem & 3;
    int xi  = (j < 2) ? j : (j + 128);
    int col = (xb + xi - 2) & 1023;
    int rA  = (rb + p - 2) & 1023;
    int rB  = (rA + 8) & 1023;
    const float* base = src + (((size_t)(img * 3 + ch)) << 20);
    smx[ch][p][xi] = make_float2(__ldg(base + (rA << 10) + col),
                                 __ldg(base + (rB << 10) + col));
}

// 8 packed FMAs: one weight pair against window rows base..base+7
__device__ __forceinline__ void fma8(ull* accrow, const ull* base, ull w) {
    #pragma unroll
    for (int p = 0; p < 8; ++p)
        fma2(accrow[p], base[p], w);
}
// 12 conflict-free LDS.64: one column window, all pair-rows
__device__ __forceinline__ void load_window(ull* rv, const float2* colbase, int kx) {
    #pragma unroll
    for (int p = 0; p < 12; ++p)
        rv[p] = *reinterpret_cast<const ull*>(colbase + p * 132 + kx);
}
// pass-A chunk: co=0,1 -> s=0..9 (5 weight LDS.128, 80 FFMA2), order as R5/R6
__device__ __forceinline__ void fchunk2(ull (*acc)[8], const ull* rv, const ull* wrow) {
    const ulonglong2* wv = reinterpret_cast<const ulonglong2*>(wrow);
    #pragma unroll
    for (int j = 0; j < 5; ++j) {
        ulonglong2 q = wv[j];
        const int s0 = 2 * j;
        const int s1 = 2 * j + 1;
        fma8(acc[s0 / 5], rv + (s0 % 5), q.x);
        fma8(acc[s1 / 5], rv + (s1 % 5), q.y);
    }
}
// pass-B chunk: co=2 -> s=10..14 (2 weight LDS.128 + 1 LDS.64, 40 FFMA2)
__device__ __forceinline__ void fchunk1(ull* acc2, const ull* rv, const ull* wrow) {
    ulonglong2 q = *reinterpret_cast<const ulonglong2*>(wrow + 10);
    fma8(acc2, rv + 0, q.x);
    fma8(acc2, rv + 1, q.y);
    q = *reinterpret_cast<const ulonglong2*>(wrow + 12);
    fma8(acc2, rv + 2, q.x);
    fma8(acc2, rv + 3, q.y);
    fma8(acc2, rv + 4, wrow[14]);
}

// Block: 128 threads. Tile: 128 cols x 16 rows x 3 channels.
// Thread owns ONE column; smem pair layout smx[ch][p][xi] = (row rb+p-2, rb+p+6).
// Two accumulation passes over the same windows (co{0,1} then co2) cap live
// registers at ~100 -> 5 blocks/SM for finer load-phase interleave.
__global__ void __launch_bounds__(128, 5) ca_step(const float* __restrict__ src,
                                                  float* __restrict__ dst)
{
    __shared__ __align__(16) float2 smx[3][12][132];
    __shared__ __align__(16) ull    wS[240];

    const int tid = threadIdx.x;
    const int xb  = blockIdx.x * 128;
    const int rb  = blockIdx.y * 16;
    const int img = blockIdx.z;

    // ---- weights -> smem ----
    if (tid < 120) {
        wS[tid]       = g_wpack[tid];
        wS[tid + 120] = g_wpack[tid + 120];
    }

    // ---- vectorized interior tile load (R6-proven) ----
    {
        const int v  = tid & 31;
        const int pq = tid >> 5;
        #pragma unroll
        for (int ch = 0; ch < 3; ++ch) {
            const float* cbase = src + (((size_t)(img * 3 + ch)) << 20) + xb + v * 4;
            #pragma unroll
            for (int k = 0; k < 3; ++k) {
                int p  = k * 4 + pq;
                int rA = (rb + p - 2) & 1023;
                int rB = (rA + 8) & 1023;
                float4 a = *reinterpret_cast<const float4*>(cbase + (rA << 10));
                float4 b = *reinterpret_cast<const float4*>(cbase + (rB << 10));
                float4* s = reinterpret_cast<float4*>(&smx[ch][p][2 + v * 4]);
                s[0] = make_float4(a.x, b.x, a.y, b.y);
                s[1] = make_float4(a.z, b.z, a.w, b.w);
            }
        }
    }
    halo_load(src, smx, tid, xb, rb, img);
    if (tid < 16)
        halo_load(src, smx, tid + 128, xb, rb, img);
    __syncthreads();

    const float2* cb0 = &smx[0][0][tid];
    const float2* cb1 = &smx[1][0][tid];
    const float2* cb2 = &smx[2][0][tid];
    const int col = xb + tid;

    ull rvA[12], rvB[12];

    // ================= pass A : out-channels 0,1 =================
    {
        ull acc[2][8];
        #pragma unroll
        for (int co = 0; co < 2; ++co)
            #pragma unroll
            for (int p = 0; p < 8; ++p)
                acc[co][p] = 0ull;

        load_window(rvA, cb0, 0);
        load_window(rvB, cb0, 1);  fchunk2(acc, rvA, &wS[0 * 80 + 0 * 16]);
        load_window(rvA, cb0, 2);  fchunk2(acc, rvB, &wS[0 * 80 + 1 * 16]);
        load_window(rvB, cb0, 3);  fchunk2(acc, rvA, &wS[0 * 80 + 2 * 16]);
        load_window(rvA, cb0, 4);  fchunk2(acc, rvB, &wS[0 * 80 + 3 * 16]);
        load_window(rvB, cb1, 0);  fchunk2(acc, rvA, &wS[0 * 80 + 4 * 16]);
        load_window(rvA, cb1, 1);  fchunk2(acc, rvB, &wS[1 * 80 + 0 * 16]);
        load_window(rvB, cb1, 2);  fchunk2(acc, rvA, &wS[1 * 80 + 1 * 16]);
        load_window(rvA, cb1, 3);  fchunk2(acc, rvB, &wS[1 * 80 + 2 * 16]);
        load_window(rvB, cb1, 4);  fchunk2(acc, rvA, &wS[1 * 80 + 3 * 16]);
        load_window(rvA, cb2, 0);  fchunk2(acc, rvB, &wS[1 * 80 + 4 * 16]);
        load_window(rvB, cb2, 1);  fchunk2(acc, rvA, &wS[2 * 80 + 0 * 16]);
        load_window(rvA, cb2, 2);  fchunk2(acc, rvB, &wS[2 * 80 + 1 * 16]);
        load_window(rvB, cb2, 3);  fchunk2(acc, rvA, &wS[2 * 80 + 2 * 16]);
        load_window(rvA, cb2, 4);  fchunk2(acc, rvB, &wS[2 * 80 + 3 * 16]);
                                   fchunk2(acc, rvA, &wS[2 * 80 + 4 * 16]);

        #pragma unroll
        for (int co = 0; co < 2; ++co) {
            float* ob = dst + (((size_t)(img * 3 + co)) << 20) + col;
            #pragma unroll
            for (int p = 0; p < 8; ++p) {
                float2 y  = unpack2(acc[co][p]);
                float2 xp = smx[co][p + 2][tid + 2];
                ob[(rb + p)     << 10] = __saturatef(fmaf(fmaxf(y.x, 0.0f), 0.1f, xp.x));
                ob[(rb + p + 8) << 10] = __saturatef(fmaf(fmaxf(y.y, 0.0f), 0.1f, xp.y));
            }
        }
    }

    // ================= pass B : out-channel 2 =================
    {
        ull acc2[8];
        #pragma unroll
        for (int p = 0; p < 8; ++p)
            acc2[p] = 0ull;

        load_window(rvA, cb0, 0);
        load_window(rvB, cb0, 1);  fchunk1(acc2, rvA, &wS[0 * 80 + 0 * 16]);
        load_window(rvA, cb0, 2);  fchunk1(acc2, rvB, &wS[0 * 80 + 1 * 16]);
        load_window(rvB, cb0, 3);  fchunk1(acc2, rvA, &wS[0 * 80 + 2 * 16]);
        load_window(rvA, cb0, 4);  fchunk1(acc2, rvB, &wS[0 * 80 + 3 * 16]);
        load_window(rvB, cb1, 0);  fchunk1(acc2, rvA, &wS[0 * 80 + 4 * 16]);
        load_window(rvA, cb1, 1);  fchunk1(acc2, rvB, &wS[1 * 80 + 0 * 16]);
        load_window(rvB, cb1, 2);  fchunk1(acc2, rvA, &wS[1 * 80 + 1 * 16]);
        load_window(rvA, cb1, 3);  fchunk1(acc2, rvB, &wS[1 * 80 + 2 * 16]);
        load_window(rvB, cb1, 4);  fchunk1(acc2, rvA, &wS[1 * 80 + 3 * 16]);
        load_window(rvA, cb2, 0);  fchunk1(acc2, rvB, &wS[1 * 80 + 4 * 16]);
        load_window(rvB, cb2, 1);  fchunk1(acc2, rvA, &wS[2 * 80 + 0 * 16]);
        load_window(rvA, cb2, 2);  fchunk1(acc2, rvB, &wS[2 * 80 + 1 * 16]);
        load_window(rvB, cb2, 3);  fchunk1(acc2, rvA, &wS[2 * 80 + 2 * 16]);
        load_window(rvA, cb2, 4);  fchunk1(acc2, rvB, &wS[2 * 80 + 3 * 16]);
                                   fchunk1(acc2, rvA, &wS[2 * 80 + 4 * 16]);

        float* ob = dst + (((size_t)(img * 3 + 2)) << 20) + col;
        #pragma unroll
        for (int p = 0; p < 8; ++p) {
            float2 y  = unpack2(acc2[p]);
            float2 xp = smx[2][p + 2][tid + 2];
            ob[(rb + p)     << 10] = __saturatef(fmaf(fmaxf(y.x, 0.0f), 0.1f, xp.x));
            ob[(rb + p + 8) << 10] = __saturatef(fmaf(fmaxf(y.y, 0.0f), 0.1f, xp.y));
        }
    }
}

extern "C" void kernel_launch(void* const* d_in, const int* in_sizes, int n_in,
                              void* d_out, int out_size)
{
    const float* x = (const float*)d_in[0];
    const float* W = (const float*)d_in[1];
    float* out = (float*)d_out;

    float* scratch = nullptr;
    cudaGetSymbolAddress((void**)&scratch, g_buf);

    pack_w<<<1, 256>>>(W);

    dim3 grid(8, 64, 16);   // 1024/128 cols, 1024/16 rows, 16 images
    dim3 block(128);

    const float* src = x;
    for (int s = 0; s < 10; ++s) {
        float* dst = (s & 1) ? out : scratch;  // step 9 (last) lands in d_out
        ca_step<<<grid, block>>>(src, dst);
        src = dst;
    }
}

// round 11
// speedup vs baseline: 2.6140x; 2.6140x over previous
#include <cuda_runtime.h>

typedef unsigned long long ull;

// 201 MB ping-pong scratch (allocation-free rule: __device__ global)
__device__ float g_buf[16u * 3u * 1024u * 1024u];
// pre-packed (w,w) f32x2 weights, layout [ci][kx][s=co*5+ky] padded to 16 (16B-aligned)
__device__ ull   g_wpack[240];

__device__ __forceinline__ ull pack2(float lo, float hi) {
    ull r;
    asm("mov.b64 %0, {%1, %2};" : "=l"(r) : "f"(lo), "f"(hi));
    return r;
}
__device__ __forceinline__ float2 unpack2(ull v) {
    float2 r;
    asm("mov.b64 {%0, %1}, %2;" : "=f"(r.x), "=f"(r.y) : "l"(v));
    return r;
}
// packed fp32x2 FMA (FFMA2) -- only reachable via PTX fma.rn.f32x2
__device__ __forceinline__ void fma2(ull& d, ull a, ull b) {
    asm("fma.rn.f32x2 %0, %1, %2, %0;" : "+l"(d) : "l"(a), "l"(b));
}

// prep: broadcast-pack weights once; W is OIHW [co][ci][ky][kx] = [3][3][5][5]
__global__ void pack_w(const float* __restrict__ W) {
    int i = threadIdx.x;
    if (i >= 240) return;
    int ci = i / 80;
    int r  = i - ci * 80;
    int kx = r / 16;
    int s  = r - kx * 16;
    float w = 0.0f;
    if (s < 15) {
        int co = s / 5;
        int ky = s - co * 5;
        w = W[co * 75 + ci * 25 + ky * 5 + kx];
    }
    g_wpack[i] = pack2(w, w);
}

__device__ __forceinline__ void halo_load(const float* __restrict__ src,
                                          float2 (*smx)[12][132],
                                          int i, int xb, int rb, int img)
{
    // i in [0,144): 3ch x 12 pair-rows x 4 wrap columns
    int ch  = i / 48;
    int rem = i - ch * 48;
    int p   = rem >> 2;
    int j   = rem & 3;
    int xi  = (j < 2) ? j : (j + 128);
    int col = (xb + xi - 2) & 1023;
    int rA  = (rb + p - 2) & 1023;
    int rB  = (rA + 8) & 1023;
    const float* base = src + (((size_t)(img * 3 + ch)) << 20);
    smx[ch][p][xi] = make_float2(__ldg(base + (rA << 10) + col),
                                 __ldg(base + (rB << 10) + col));
}

// 8 packed FMAs: one weight pair against window rows base..base+7
__device__ __forceinline__ void fma8(ull* accrow, const ull* base, ull w) {
    #pragma unroll
    for (int p = 0; p < 8; ++p)
        fma2(accrow[p], base[p], w);
}

// Block: 128 threads. Tile: 128 cols x 16 rows x 3 channels.
// Thread owns ONE column (col = xb + tid) and 16 rows as 8 vertical f32x2 pairs
// (rows r, r+8).  smem pair layout: smx[ch][p][xi] = (row rb+p-2, row rb+p+6),
// so output pair p with tap ky reads input pair p+ky at col tid+kx.
// LDS.64 window loads have 8B lane stride -> conflict-free.
// R5 body (94 regs natural) at 5 blocks/SM: 20 warps/SM for latency hiding +
// 5 independent blocks to interleave load/store phases.
__global__ void __launch_bounds__(128, 5) ca_step(const float* __restrict__ src,
                                                  float* __restrict__ dst)
{
    __shared__ __align__(16) float2 smx[3][12][132];
    __shared__ __align__(16) ull    wS[240];

    const int tid = threadIdx.x;
    const int xb  = blockIdx.x * 128;
    const int rb  = blockIdx.y * 16;
    const int img = blockIdx.z;

    // ---- weights -> smem (broadcast source for the hot loop) ----
    if (tid < 120) {
        wS[tid]       = g_wpack[tid];
        wS[tid + 120] = g_wpack[tid + 120];
    }

    // ---- vectorized interior tile load: div/mod-free ----
    {
        const int v  = tid & 31;
        const int pq = tid >> 5;     // 0..3
        #pragma unroll
        for (int ch = 0; ch < 3; ++ch) {
            const float* cbase = src + (((size_t)(img * 3 + ch)) << 20) + xb + v * 4;
            #pragma unroll
            for (int k = 0; k < 3; ++k) {
                int p  = k * 4 + pq;                 // 0..11
                int rA = (rb + p - 2) & 1023;
                int rB = (rA + 8) & 1023;
                float4 a = *reinterpret_cast<const float4*>(cbase + (rA << 10));
                float4 b = *reinterpret_cast<const float4*>(cbase + (rB << 10));
                float4* s = reinterpret_cast<float4*>(&smx[ch][p][2 + v * 4]);
                s[0] = make_float4(a.x, b.x, a.y, b.y);
                s[1] = make_float4(a.z, b.z, a.w, b.w);
            }
        }
    }
    // ---- halo columns (wrap): 144 items on 128 threads -> two trips ----
    halo_load(src, smx, tid, xb, rb, img);
    if (tid < 16)
        halo_load(src, smx, tid + 128, xb, rb, img);
    __syncthreads();

    // ---- conv accumulation: 3 out-channels x 8 row-pairs, packed f32x2 ----
    ull acc[3][8];
    #pragma unroll
    for (int co = 0; co < 3; ++co)
        #pragma unroll
        for (int p = 0; p < 8; ++p)
            acc[co][p] = 0ull;

    #pragma unroll 1
    for (int ci = 0; ci < 3; ++ci) {
        const float2* colbase = &smx[ci][0][tid];
        const ull*    wbase   = &wS[ci * 80];
        #pragma unroll 1          // rolled kx: the layout ptxas pairs cleanly (R2/R5-proven)
        for (int kx = 0; kx < 5; ++kx) {
            // 12 conflict-free LDS.64: column tid+kx, all pair-rows
            ull rv[12];
            #pragma unroll
            for (int p = 0; p < 12; ++p)
                rv[p] = *reinterpret_cast<const ull*>(colbase + p * 132 + kx);

            // weights for this (ci,kx): 15 pairs, fetched 2-at-a-time via LDS.128.
            // s = co*5+ky ascending -> identical accumulation order throughout.
            const ulonglong2* wv =
                reinterpret_cast<const ulonglong2*>(wbase + kx * 16);
            #pragma unroll
            for (int j = 0; j < 7; ++j) {
                ulonglong2 q = wv[j];
                const int s0 = 2 * j;
                const int s1 = 2 * j + 1;
                fma8(acc[s0 / 5], rv + (s0 % 5), q.x);
                fma8(acc[s1 / 5], rv + (s1 % 5), q.y);
            }
            {
                ull w14 = *(wbase + kx * 16 + 14);   // s=14 -> co=2, ky=4
                fma8(acc[2], rv + 4, w14);
            }
        }
    }

    // ---- epilogue: out = clip(x + 0.1*relu(y), 0, 1) ----
    const int col = xb + tid;
    #pragma unroll
    for (int co = 0; co < 3; ++co) {
        float* ob = dst + (((size_t)(img * 3 + co)) << 20) + col;
        #pragma unroll
        for (int p = 0; p < 8; ++p) {
            float2 y  = unpack2(acc[co][p]);
            float2 xp = smx[co][p + 2][tid + 2];   // (row rb+p, row rb+p+8)
            ob[(rb + p)     << 10] = __saturatef(fmaf(fmaxf(y.x, 0.0f), 0.1f, xp.x));
            ob[(rb + p + 8) << 10] = __saturatef(fmaf(fmaxf(y.y, 0.0f), 0.1f, xp.y));
        }
    }
}

extern "C" void kernel_launch(void* const* d_in, const int* in_sizes, int n_in,
                              void* d_out, int out_size)
{
    const float* x = (const float*)d_in[0];
    const float* W = (const float*)d_in[1];
    float* out = (float*)d_out;

    float* scratch = nullptr;
    cudaGetSymbolAddress((void**)&scratch, g_buf);

    pack_w<<<1, 256>>>(W);

    dim3 grid(8, 64, 16);   // 1024/128 cols, 1024/16 rows, 16 images
    dim3 block(128);

    const float* src = x;
    for (int s = 0; s < 10; ++s) {
        float* dst = (s & 1) ? out : scratch;  // step 9 (last) lands in d_out
        ca_step<<<grid, block>>>(src, dst);
        src = dst;
    }
}

// round 12
// speedup vs baseline: 3.0419x; 1.1637x over previous
#include <cuda_runtime.h>

typedef unsigned long long ull;

// image-paired ping-pong buffers: P[pair][ch][row][col] = float2(x[img p], x[img p+8])
// pair p in 0..7.  ~201 MB each (allocation-free rule: __device__ globals)
__device__ float2 g_p0[8u * 3u * 1024u * 1024u];
__device__ float2 g_p1[8u * 3u * 1024u * 1024u];
// pre-packed (w,w) f32x2 weights, layout [ci][kx][s=co*5+ky] padded to 16
__device__ ull    g_wpack[240];

__device__ __forceinline__ ull pack2(float lo, float hi) {
    ull r;
    asm("mov.b64 %0, {%1, %2};" : "=l"(r) : "f"(lo), "f"(hi));
    return r;
}
__device__ __forceinline__ float2 unpack2(ull v) {
    float2 r;
    asm("mov.b64 {%0, %1}, %2;" : "=f"(r.x), "=f"(r.y) : "l"(v));
    return r;
}
// packed fp32x2 FMA (FFMA2) -- only reachable via PTX fma.rn.f32x2
__device__ __forceinline__ void fma2(ull& d, ull a, ull b) {
    asm("fma.rn.f32x2 %0, %1, %2, %0;" : "+l"(d) : "l"(a), "l"(b));
}

// prep: broadcast-pack weights once; W is OIHW [co][ci][ky][kx] = [3][3][5][5]
__global__ void pack_w(const float* __restrict__ W) {
    int i = threadIdx.x;
    if (i >= 240) return;
    int ci = i / 80;
    int r  = i - ci * 80;
    int kx = r / 16;
    int s  = r - kx * 16;
    float w = 0.0f;
    if (s < 15) {
        int co = s / 5;
        int ky = s - co * 5;
        w = W[co * 75 + ci * 25 + ky * 5 + kx];
    }
    g_wpack[i] = pack2(w, w);
}

// 8 packed FMAs: one weight pair against window rows base..base+7
__device__ __forceinline__ void fma8(ull* accrow, const ull* base, ull w) {
    #pragma unroll
    for (int p = 0; p < 8; ++p)
        fma2(accrow[p], base[p], w);
}
// 12 conflict-free LDS.64: one column window, all window rows
__device__ __forceinline__ void load_window(ull* rv, const float2* colbase, int kx) {
    #pragma unroll
    for (int p = 0; p < 12; ++p)
        rv[p] = *reinterpret_cast<const ull*>(colbase + p * 132 + kx);
}
// one (ci,kx) chunk: 8 weight LDS.128 pairs + 120 FFMA2 (R5/R6-proven order)
__device__ __forceinline__ void fchunk(ull (*acc)[8], const ull* rv, const ull* wrow) {
    const ulonglong2* wv = reinterpret_cast<const ulonglong2*>(wrow);
    #pragma unroll
    for (int j = 0; j < 7; ++j) {
        ulonglong2 q = wv[j];
        const int s0 = 2 * j;
        const int s1 = 2 * j + 1;
        fma8(acc[s0 / 5], rv + (s0 % 5), q.x);
        fma8(acc[s1 / 5], rv + (s1 % 5), q.y);
    }
    fma8(acc[2], rv + 4, wrow[14]);   // s=14 -> co=2, ky=4
}

// Block: 128 threads. Tile: 128 cols x 8 rows x 3 ch x 2 images (paired).
// smx[ch][r][xi] = float2(imgA, imgB) at (row rb+r-2, col xb+xi-2).
// Output row rb+p with tap ky reads window row p+ky at col tid+kx.
// Hot loop is byte-identical to R6; pairing axis is the batch, so paired
// gmem (steps 1..8) loads/stores with ZERO shuffling.
template <int INP, int OUTP>
__global__ void __launch_bounds__(128, 4) ca_step(const float*  __restrict__ srcN,
                                                  const float2* __restrict__ srcP,
                                                  float*        __restrict__ dstN,
                                                  float2*       __restrict__ dstP)
{
    __shared__ __align__(16) float2 smx[3][12][132];
    __shared__ __align__(16) ull    wS[240];

    const int tid  = threadIdx.x;
    const int xb   = blockIdx.x * 128;
    const int rb   = blockIdx.y * 8;
    const int pair = blockIdx.z;          // images (pair, pair+8)

    // ---- weights -> smem ----
    if (tid < 120) {
        wS[tid]       = g_wpack[tid];
        wS[tid + 120] = g_wpack[tid + 120];
    }

    if (INP) {
        // ===== paired loader: pure contiguous 16B copies, no shuffle =====
        #pragma unroll
        for (int ch = 0; ch < 3; ++ch) {
            const float2* pbase = srcP + (((size_t)(pair * 3 + ch)) << 20);
            #pragma unroll
            for (int k = 0; k < 6; ++k) {
                int j   = k * 128 + tid;       // 0..767
                int row = j >> 6;              // 0..11
                int c2  = j & 63;              // 16B chunk (2 cols)
                const float4* sp = reinterpret_cast<const float4*>(
                    pbase + (((rb + row - 2) & 1023) << 10) + xb + 2 * c2);
                *reinterpret_cast<float4*>(&smx[ch][row][2 + 2 * c2]) = *sp;
            }
        }
        // halo: 3ch x 12 rows x 2 sides; wrapped col pairs are gmem-contiguous
        if (tid < 72) {
            int ch   = tid / 24;
            int rem  = tid - ch * 24;
            int row  = rem >> 1;
            int side = rem & 1;
            int gcol = side ? ((xb + 128) & 1023) : ((xb - 2) & 1023);
            int sidx = side ? 130 : 0;
            const float2* pbase = srcP + (((size_t)(pair * 3 + ch)) << 20);
            const float4* sp = reinterpret_cast<const float4*>(
                pbase + (((rb + row - 2) & 1023) << 10) + gcol);
            *reinterpret_cast<float4*>(&smx[ch][row][sidx]) = *sp;
        }
    } else {
        // ===== normal loader (step 0): interleave imgs (pair, pair+8) =====
        #pragma unroll
        for (int ch = 0; ch < 3; ++ch) {
            const float* baseA = srcN + (((size_t)(pair * 3 + ch)) << 20);
            const float* baseB = baseA + (((size_t)24) << 20);
            #pragma unroll
            for (int k = 0; k < 3; ++k) {
                int j   = k * 128 + tid;       // 0..383
                int row = j >> 5;              // 0..11
                int g   = j & 31;              // float4 group (4 cols)
                int off = (((rb + row - 2) & 1023) << 10) + xb + 4 * g;
                float4 a = *reinterpret_cast<const float4*>(baseA + off);
                float4 b = *reinterpret_cast<const float4*>(baseB + off);
                float4* s = reinterpret_cast<float4*>(&smx[ch][row][2 + 4 * g]);
                s[0] = make_float4(a.x, b.x, a.y, b.y);
                s[1] = make_float4(a.z, b.z, a.w, b.w);
            }
        }
        if (tid < 72) {
            int ch   = tid / 24;
            int rem  = tid - ch * 24;
            int row  = rem >> 1;
            int side = rem & 1;
            int gcol = side ? ((xb + 128) & 1023) : ((xb - 2) & 1023);
            int sidx = side ? 130 : 0;
            const float* baseA = srcN + (((size_t)(pair * 3 + ch)) << 20);
            const float* baseB = baseA + (((size_t)24) << 20);
            int off = (((rb + row - 2) & 1023) << 10) + gcol;
            float2 a = *reinterpret_cast<const float2*>(baseA + off);
            float2 b = *reinterpret_cast<const float2*>(baseB + off);
            *reinterpret_cast<float4*>(&smx[ch][row][sidx]) =
                make_float4(a.x, b.x, a.y, b.y);
        }
    }
    __syncthreads();

    // ---- conv accumulation: 3 out-channels x 8 rows, batch-packed f32x2 ----
    ull acc[3][8];
    #pragma unroll
    for (int co = 0; co < 3; ++co)
        #pragma unroll
        for (int p = 0; p < 8; ++p)
            acc[co][p] = 0ull;

    const float2* cb0 = &smx[0][0][tid];
    const float2* cb1 = &smx[1][0][tid];
    const float2* cb2 = &smx[2][0][tid];

    ull rvA[12], rvB[12];
    // 15 chunks (ci,kx), 2-deep pipeline (R6-proven, byte-identical)
    load_window(rvA, cb0, 0);
    load_window(rvB, cb0, 1);  fchunk(acc, rvA, &wS[0 * 80 + 0 * 16]);
    load_window(rvA, cb0, 2);  fchunk(acc, rvB, &wS[0 * 80 + 1 * 16]);
    load_window(rvB, cb0, 3);  fchunk(acc, rvA, &wS[0 * 80 + 2 * 16]);
    load_window(rvA, cb0, 4);  fchunk(acc, rvB, &wS[0 * 80 + 3 * 16]);
    load_window(rvB, cb1, 0);  fchunk(acc, rvA, &wS[0 * 80 + 4 * 16]);
    load_window(rvA, cb1, 1);  fchunk(acc, rvB, &wS[1 * 80 + 0 * 16]);
    load_window(rvB, cb1, 2);  fchunk(acc, rvA, &wS[1 * 80 + 1 * 16]);
    load_window(rvA, cb1, 3);  fchunk(acc, rvB, &wS[1 * 80 + 2 * 16]);
    load_window(rvB, cb1, 4);  fchunk(acc, rvA, &wS[1 * 80 + 3 * 16]);
    load_window(rvA, cb2, 0);  fchunk(acc, rvB, &wS[1 * 80 + 4 * 16]);
    load_window(rvB, cb2, 1);  fchunk(acc, rvA, &wS[2 * 80 + 0 * 16]);
    load_window(rvA, cb2, 2);  fchunk(acc, rvB, &wS[2 * 80 + 1 * 16]);
    load_window(rvB, cb2, 3);  fchunk(acc, rvA, &wS[2 * 80 + 2 * 16]);
    load_window(rvA, cb2, 4);  fchunk(acc, rvB, &wS[2 * 80 + 3 * 16]);
                               fchunk(acc, rvA, &wS[2 * 80 + 4 * 16]);

    // ---- epilogue: out = clip(x + 0.1*relu(y), 0, 1) ----
    const int col = xb + tid;
    #pragma unroll
    for (int co = 0; co < 3; ++co) {
        float2* obP = OUTP ? dstP + (((size_t)(pair * 3 + co)) << 20) + col : nullptr;
        float*  obA = OUTP ? nullptr : dstN + (((size_t)(pair * 3 + co)) << 20) + col;
        float*  obB = OUTP ? nullptr : obA + (((size_t)24) << 20);
        #pragma unroll
        for (int p = 0; p < 8; ++p) {
            float2 y  = unpack2(acc[co][p]);
            float2 xp = smx[co][p + 2][tid + 2];   // input (imgA, imgB) at out loc
            float a = __saturatef(fmaf(fmaxf(y.x, 0.0f), 0.1f, xp.x));
            float b = __saturatef(fmaf(fmaxf(y.y, 0.0f), 0.1f, xp.y));
            if (OUTP) {
                obP[(rb + p) << 10] = make_float2(a, b);   // coalesced STG.64
            } else {
                obA[(rb + p) << 10] = a;
                obB[(rb + p) << 10] = b;
            }
        }
    }
}

extern "C" void kernel_launch(void* const* d_in, const int* in_sizes, int n_in,
                              void* d_out, int out_size)
{
    const float* x = (const float*)d_in[0];
    const float* W = (const float*)d_in[1];
    float* out = (float*)d_out;

    float2 *p0 = nullptr, *p1 = nullptr;
    cudaGetSymbolAddress((void**)&p0, g_p0);
    cudaGetSymbolAddress((void**)&p1, g_p1);

    pack_w<<<1, 256>>>(W);

    dim3 grid(8, 128, 8);   // 1024/128 cols, 1024/8 rows, 8 image pairs
    dim3 block(128);

    // s0: normal x -> paired p0
    ca_step<0, 1><<<grid, block>>>(x, nullptr, nullptr, p0);
    // s1..s8: paired ping-pong (zero-shuffle loads/stores)
    float2* pin = p0;
    float2* pout = p1;
    for (int s = 1; s <= 8; ++s) {
        ca_step<1, 1><<<grid, block>>>(nullptr, pin, nullptr, pout);
        float2* t = pin; pin = pout; pout = t;
    }
    // s9: paired -> normal d_out
    ca_step<1, 0><<<grid, block>>>(nullptr, pin, out, nullptr);
}